// round 2
// baseline (speedup 1.0000x reference)
#include <cuda_runtime.h>

// Problem constants
#define Bq 16
#define Tq 1024
#define Cq 768
#define Mq (Bq*Tq)          // 16384
#define NBC (Bq*Cq)         // 12288

// -------- device scratch (static, no allocations) --------
__device__ float g_k [12582912];   // Mq*Cq
__device__ float g_v [12582912];
__device__ float g_sr[12582912];
__device__ float g_fn[12582912];
__device__ float g_fd[12582912];
__device__ float g_y [12582912];
__device__ float g_kmax[NBC];

// -------- tf32 helpers --------
__device__ __forceinline__ float to_tf32(float f){
    unsigned u;
    asm("cvt.rna.tf32.f32 %0, %1;" : "=r"(u) : "f"(f));
    return __uint_as_float(u);
}

__device__ __forceinline__ void mma8(float d[4], const float a[4], const float b[2]){
    const unsigned* A  = reinterpret_cast<const unsigned*>(a);
    const unsigned* Bb = reinterpret_cast<const unsigned*>(b);
    asm volatile(
      "mma.sync.aligned.m16n8k8.row.col.f32.tf32.tf32.f32 "
      "{%0,%1,%2,%3}, {%4,%5,%6,%7}, {%8,%9}, {%0,%1,%2,%3};\n"
      : "+f"(d[0]), "+f"(d[1]), "+f"(d[2]), "+f"(d[3])
      : "r"(A[0]), "r"(A[1]), "r"(A[2]), "r"(A[3]), "r"(Bb[0]), "r"(Bb[1]));
}

// -------- GEMM: C[m,n] = sum_k A[m,k] * W[n,k] --------
// MIXED=true: A is built on the fly from x via q_shift + token mix; z=blockIdx.z
//             selects (key|value|receptance) weights/mix/output; z==2 applies sigmoid.
// MIXED=false: A = g_y, W = output_w, C = d_out.
#define BM 128
#define BN 128
#define BK 32
#define PAD 36   // bank-conflict-free for frag reads: bank = (4*c + g) % 32, all distinct

template<bool MIXED>
__global__ __launch_bounds__(256, 2) void gemm_tf32(
    const float* __restrict__ x,
    const float* __restrict__ Wk, const float* __restrict__ Wv, const float* __restrict__ Wr,
    const float* __restrict__ mk, const float* __restrict__ mv, const float* __restrict__ mr,
    float* __restrict__ Cext)
{
    __shared__ float As[BM*PAD];
    __shared__ float Bs[BN*PAD];

    const float* W;
    const float* mix = nullptr;
    float* Cout;
    const float* Ap;
    int z = MIXED ? blockIdx.z : 0;
    if (MIXED) {
        W    = (z==0) ? Wk : (z==1) ? Wv : Wr;
        mix  = (z==0) ? mk : (z==1) ? mv : mr;
        Cout = (z==0) ? g_k : (z==1) ? g_v : g_sr;
        Ap   = x;
    } else {
        W = Wk; Cout = Cext; Ap = g_y;
    }

    const int m0 = blockIdx.y * BM;
    const int n0 = blockIdx.x * BN;
    const int tid  = threadIdx.x;
    const int lane = tid & 31;
    const int wid  = tid >> 5;
    const int wm = wid & 3;        // 4 warps along M (32 rows each)
    const int wn = wid >> 2;       // 2 warps along N (64 cols each)
    const int grp8 = lane >> 2;    // mma group id
    const int c4   = lane & 3;     // mma thread-in-group
    const int lrow = tid >> 3;     // 0..31
    const int lk   = (tid & 7) << 2;

    float acc[2][8][4];
    #pragma unroll
    for (int i=0;i<2;i++)
      #pragma unroll
      for (int j=0;j<8;j++)
        #pragma unroll
        for (int q=0;q<4;q++) acc[i][j][q] = 0.f;

    for (int kt = 0; kt < Cq; kt += BK) {
        // ---- A tile (128 x 32) ----
        #pragma unroll
        for (int p=0;p<4;p++){
            int row = p*32 + lrow;
            int m = m0 + row;
            int kk = kt + lk;
            float4 a4;
            if (MIXED) {
                int t  = m & (Tq-1);
                int bb = m >> 10;
                int grp = kk / 192;      // q_shift quadrant (kk..kk+3 in same quadrant)
                int wq = t & 31, hq = t >> 5;
                int tt; bool valid;
                if      (grp==0) { tt = t-1;  valid = (wq > 0);  }
                else if (grp==1) { tt = t+1;  valid = (wq < 31); }
                else if (grp==2) { tt = t-32; valid = (hq > 0);  }
                else             { tt = t+32; valid = (hq < 31); }
                float4 xv = *reinterpret_cast<const float4*>(Ap + (size_t)m*Cq + kk);
                float4 xs = make_float4(0.f,0.f,0.f,0.f);
                if (valid)
                    xs = *reinterpret_cast<const float4*>(Ap + ((size_t)(bb<<10) + tt)*Cq + kk);
                float4 mx = *reinterpret_cast<const float4*>(mix + kk);
                a4.x = mx.x*(xv.x - xs.x) + xs.x;   // mix*x + (1-mix)*xs
                a4.y = mx.y*(xv.y - xs.y) + xs.y;
                a4.z = mx.z*(xv.z - xs.z) + xs.z;
                a4.w = mx.w*(xv.w - xs.w) + xs.w;
            } else {
                a4 = *reinterpret_cast<const float4*>(Ap + (size_t)m*Cq + kk);
            }
            float* dst = &As[row*PAD + lk];
            dst[0] = to_tf32(a4.x); dst[1] = to_tf32(a4.y);
            dst[2] = to_tf32(a4.z); dst[3] = to_tf32(a4.w);
        }
        // ---- B tile (128 x 32), W is row-major [n, k] ----
        #pragma unroll
        for (int p=0;p<4;p++){
            int n = p*32 + lrow;
            float4 w4 = *reinterpret_cast<const float4*>(W + (size_t)(n0+n)*Cq + kt + lk);
            float* dst = &Bs[n*PAD + lk];
            dst[0] = to_tf32(w4.x); dst[1] = to_tf32(w4.y);
            dst[2] = to_tf32(w4.z); dst[3] = to_tf32(w4.w);
        }
        __syncthreads();

        #pragma unroll
        for (int ks=0; ks<4; ks++){
            int kb = ks*8;
            float af[2][4];
            #pragma unroll
            for (int i=0;i<2;i++){
                int r = wm*32 + i*16;
                af[i][0] = As[(r+grp8  )*PAD + kb + c4    ];
                af[i][1] = As[(r+grp8+8)*PAD + kb + c4    ];
                af[i][2] = As[(r+grp8  )*PAD + kb + c4 + 4];
                af[i][3] = As[(r+grp8+8)*PAD + kb + c4 + 4];
            }
            float bf[8][2];
            #pragma unroll
            for (int j=0;j<8;j++){
                int n = wn*64 + j*8 + grp8;
                bf[j][0] = Bs[n*PAD + kb + c4    ];
                bf[j][1] = Bs[n*PAD + kb + c4 + 4];
            }
            #pragma unroll
            for (int i=0;i<2;i++)
                #pragma unroll
                for (int j=0;j<8;j++)
                    mma8(acc[i][j], af[i], bf[j]);
        }
        __syncthreads();
    }

    // ---- epilogue ----
    #pragma unroll
    for (int i=0;i<2;i++){
        int r = m0 + wm*32 + i*16 + grp8;
        #pragma unroll
        for (int j=0;j<8;j++){
            int col = n0 + wn*64 + j*8 + 2*c4;
            float v0 = acc[i][j][0], v1 = acc[i][j][1];
            float v2 = acc[i][j][2], v3 = acc[i][j][3];
            if (MIXED && z == 2){
                v0 = 1.f/(1.f+__expf(-v0)); v1 = 1.f/(1.f+__expf(-v1));
                v2 = 1.f/(1.f+__expf(-v2)); v3 = 1.f/(1.f+__expf(-v3));
            }
            *reinterpret_cast<float2*>(Cout + (size_t)r*Cq + col)     = make_float2(v0, v1);
            *reinterpret_cast<float2*>(Cout + (size_t)(r+8)*Cq + col) = make_float2(v2, v3);
        }
    }
}

// -------- bi_wkv forward: kmax + exclusive forward scan (writes fn, fd) --------
__global__ void wkv_fwd(const float* __restrict__ decay)
{
    int gid = blockIdx.x * blockDim.x + threadIdx.x;
    if (gid >= NBC) return;
    int b = gid / Cq, c = gid % Cq;
    size_t base = (size_t)b * Tq * Cq + c;

    float km = -3.4e38f;
    #pragma unroll 4
    for (int t = 0; t < Tq; t++)
        km = fmaxf(km, g_k[base + (size_t)t*Cq]);
    g_kmax[gid] = km;

    float w  = decay[c] * (1.0f / (float)Tq);
    float ew = __expf(-__expf(w));

    float num = 0.f, den = 0.f;
    for (int t = 0; t < Tq; t++){
        size_t idx = base + (size_t)t*Cq;
        g_fn[idx] = num;           // exclusive prefix (pre-update carry)
        g_fd[idx] = den;
        float kk = g_k[idx], vv = g_v[idx];
        float ek = __expf(kk - km);
        num = fmaf(ew, num, ek * vv);
        den = fmaf(ew, den, ek);
    }
}

// -------- bi_wkv backward scan + combine + sr multiply (writes y) --------
__global__ void wkv_bwd(const float* __restrict__ decay, const float* __restrict__ first)
{
    int gid = blockIdx.x * blockDim.x + threadIdx.x;
    if (gid >= NBC) return;
    int b = gid / Cq, c = gid % Cq;
    size_t base = (size_t)b * Tq * Cq + c;

    float km = g_kmax[gid];
    float w  = decay[c] * (1.0f / (float)Tq);
    float ew = __expf(-__expf(w));
    float u  = first[c] * (1.0f / (float)Tq);

    float num = 0.f, den = 0.f;
    for (int t = Tq - 1; t >= 0; t--){
        size_t idx = base + (size_t)t*Cq;
        float kk = g_k[idx], vv = g_v[idx];
        float ek = __expf(kk - km);
        float eu = __expf(u + kk - km);
        float out = (g_fn[idx] + num + eu * vv) / (g_fd[idx] + den + eu);
        g_y[idx] = g_sr[idx] * out;
        num = fmaf(ew, num, ek * vv);
        den = fmaf(ew, den, ek);
    }
}

extern "C" void kernel_launch(void* const* d_in, const int* in_sizes, int n_in,
                              void* d_out, int out_size)
{
    const float* x       = (const float*)d_in[0];
    const float* key_w   = (const float*)d_in[1];
    const float* value_w = (const float*)d_in[2];
    const float* recep_w = (const float*)d_in[3];
    const float* out_w   = (const float*)d_in[4];
    const float* decay   = (const float*)d_in[5];
    const float* first   = (const float*)d_in[6];
    const float* mk      = (const float*)d_in[7];
    const float* mv      = (const float*)d_in[8];
    const float* mr      = (const float*)d_in[9];
    float* out = (float*)d_out;

    // 1) k, v, sr  (fused q_shift + mix in A loader; sigmoid in z==2 epilogue)
    dim3 grid1(Cq/BN, Mq/BM, 3);
    gemm_tf32<true><<<grid1, 256>>>(x, key_w, value_w, recep_w, mk, mv, mr, nullptr);

    // 2) forward scan (+kmax), 3) backward scan + combine
    wkv_fwd<<<NBC/128, 128>>>(decay);
    wkv_bwd<<<NBC/128, 128>>>(decay, first);

    // 4) out = (sr * rwkv) @ output_w^T
    dim3 grid2(Cq/BN, Mq/BM, 1);
    gemm_tf32<false><<<grid2, 256>>>(nullptr, out_w, nullptr, nullptr,
                                     nullptr, nullptr, nullptr, out);
}

// round 3
// speedup vs baseline: 2.4705x; 2.4705x over previous
#include <cuda_runtime.h>

// Problem constants
#define Bq 16
#define Tq 1024
#define Cq 768
#define Mq (Bq*Tq)          // 16384
#define NBC (Bq*Cq)         // 12288
#define Ls 16               // chunk length
#define Ss 64               // num chunks (Ls*Ss == Tq)

// -------- device scratch (static, no allocations) --------
__device__ float g_k [12582912];   // Mq*Cq
__device__ float g_v [12582912];
__device__ float g_sr[12582912];
__device__ float g_y [12582912];
// chunk carries: [Bq][Ss][Cq]
#define CHN (Bq*Ss*Cq)
__device__ float g_cF [CHN];
__device__ float g_cFd[CHN];
__device__ float g_cB [CHN];
__device__ float g_cBd[CHN];
__device__ float g_Fin [CHN];
__device__ float g_Fdin[CHN];
__device__ float g_Bin [CHN];
__device__ float g_Bdin[CHN];

// -------- tf32 helpers --------
__device__ __forceinline__ float to_tf32(float f){
    unsigned u;
    asm("cvt.rna.tf32.f32 %0, %1;" : "=r"(u) : "f"(f));
    return __uint_as_float(u);
}

__device__ __forceinline__ void mma8(float d[4], const float a[4], const float b[2]){
    const unsigned* A  = reinterpret_cast<const unsigned*>(a);
    const unsigned* Bb = reinterpret_cast<const unsigned*>(b);
    asm volatile(
      "mma.sync.aligned.m16n8k8.row.col.f32.tf32.tf32.f32 "
      "{%0,%1,%2,%3}, {%4,%5,%6,%7}, {%8,%9}, {%0,%1,%2,%3};\n"
      : "+f"(d[0]), "+f"(d[1]), "+f"(d[2]), "+f"(d[3])
      : "r"(A[0]), "r"(A[1]), "r"(A[2]), "r"(A[3]), "r"(Bb[0]), "r"(Bb[1]));
}

// -------- GEMM: C[m,n] = sum_k A[m,k] * W[n,k] --------
#define BM 128
#define BN 128
#define BK 32
#define PAD 36

template<bool MIXED>
__global__ __launch_bounds__(256, 2) void gemm_tf32(
    const float* __restrict__ x,
    const float* __restrict__ Wk, const float* __restrict__ Wv, const float* __restrict__ Wr,
    const float* __restrict__ mk, const float* __restrict__ mv, const float* __restrict__ mr,
    float* __restrict__ Cext)
{
    __shared__ float As[BM*PAD];
    __shared__ float Bs[BN*PAD];

    const float* W;
    const float* mix = nullptr;
    float* Cout;
    const float* Ap;
    int z = MIXED ? blockIdx.z : 0;
    if (MIXED) {
        W    = (z==0) ? Wk : (z==1) ? Wv : Wr;
        mix  = (z==0) ? mk : (z==1) ? mv : mr;
        Cout = (z==0) ? g_k : (z==1) ? g_v : g_sr;
        Ap   = x;
    } else {
        W = Wk; Cout = Cext; Ap = g_y;
    }

    const int m0 = blockIdx.y * BM;
    const int n0 = blockIdx.x * BN;
    const int tid  = threadIdx.x;
    const int lane = tid & 31;
    const int wid  = tid >> 5;
    const int wm = wid & 3;
    const int wn = wid >> 2;
    const int grp8 = lane >> 2;
    const int c4   = lane & 3;
    const int lrow = tid >> 3;
    const int lk   = (tid & 7) << 2;

    float acc[2][8][4];
    #pragma unroll
    for (int i=0;i<2;i++)
      #pragma unroll
      for (int j=0;j<8;j++)
        #pragma unroll
        for (int q=0;q<4;q++) acc[i][j][q] = 0.f;

    for (int kt = 0; kt < Cq; kt += BK) {
        #pragma unroll
        for (int p=0;p<4;p++){
            int row = p*32 + lrow;
            int m = m0 + row;
            int kk = kt + lk;
            float4 a4;
            if (MIXED) {
                int t  = m & (Tq-1);
                int bb = m >> 10;
                int grp = kk / 192;
                int wq = t & 31, hq = t >> 5;
                int tt; bool valid;
                if      (grp==0) { tt = t-1;  valid = (wq > 0);  }
                else if (grp==1) { tt = t+1;  valid = (wq < 31); }
                else if (grp==2) { tt = t-32; valid = (hq > 0);  }
                else             { tt = t+32; valid = (hq < 31); }
                float4 xv = *reinterpret_cast<const float4*>(Ap + (size_t)m*Cq + kk);
                float4 xs = make_float4(0.f,0.f,0.f,0.f);
                if (valid)
                    xs = *reinterpret_cast<const float4*>(Ap + ((size_t)(bb<<10) + tt)*Cq + kk);
                float4 mx = *reinterpret_cast<const float4*>(mix + kk);
                a4.x = mx.x*(xv.x - xs.x) + xs.x;
                a4.y = mx.y*(xv.y - xs.y) + xs.y;
                a4.z = mx.z*(xv.z - xs.z) + xs.z;
                a4.w = mx.w*(xv.w - xs.w) + xs.w;
            } else {
                a4 = *reinterpret_cast<const float4*>(Ap + (size_t)m*Cq + kk);
            }
            float* dst = &As[row*PAD + lk];
            dst[0] = to_tf32(a4.x); dst[1] = to_tf32(a4.y);
            dst[2] = to_tf32(a4.z); dst[3] = to_tf32(a4.w);
        }
        #pragma unroll
        for (int p=0;p<4;p++){
            int n = p*32 + lrow;
            float4 w4 = *reinterpret_cast<const float4*>(W + (size_t)(n0+n)*Cq + kt + lk);
            float* dst = &Bs[n*PAD + lk];
            dst[0] = to_tf32(w4.x); dst[1] = to_tf32(w4.y);
            dst[2] = to_tf32(w4.z); dst[3] = to_tf32(w4.w);
        }
        __syncthreads();

        #pragma unroll
        for (int ks=0; ks<4; ks++){
            int kb = ks*8;
            float af[2][4];
            #pragma unroll
            for (int i=0;i<2;i++){
                int r = wm*32 + i*16;
                af[i][0] = As[(r+grp8  )*PAD + kb + c4    ];
                af[i][1] = As[(r+grp8+8)*PAD + kb + c4    ];
                af[i][2] = As[(r+grp8  )*PAD + kb + c4 + 4];
                af[i][3] = As[(r+grp8+8)*PAD + kb + c4 + 4];
            }
            float bf[8][2];
            #pragma unroll
            for (int j=0;j<8;j++){
                int n = wn*64 + j*8 + grp8;
                bf[j][0] = Bs[n*PAD + kb + c4    ];
                bf[j][1] = Bs[n*PAD + kb + c4 + 4];
            }
            #pragma unroll
            for (int i=0;i<2;i++)
                #pragma unroll
                for (int j=0;j<8;j++)
                    mma8(acc[i][j], af[i], bf[j]);
        }
        __syncthreads();
    }

    #pragma unroll
    for (int i=0;i<2;i++){
        int r = m0 + wm*32 + i*16 + grp8;
        #pragma unroll
        for (int j=0;j<8;j++){
            int col = n0 + wn*64 + j*8 + 2*c4;
            float v0 = acc[i][j][0], v1 = acc[i][j][1];
            float v2 = acc[i][j][2], v3 = acc[i][j][3];
            if (MIXED && z == 2){
                v0 = 1.f/(1.f+__expf(-v0)); v1 = 1.f/(1.f+__expf(-v1));
                v2 = 1.f/(1.f+__expf(-v2)); v3 = 1.f/(1.f+__expf(-v3));
            }
            *reinterpret_cast<float2*>(Cout + (size_t)r*Cq + col)     = make_float2(v0, v1);
            *reinterpret_cast<float2*>(Cout + (size_t)(r+8)*Cq + col) = make_float2(v2, v3);
        }
    }
}

// ================= chunked bi_wkv scan =================
// Recurrence num_t = ew*num_{t-1} + ekv_t decomposed over Ss chunks of Ls.
// kmax dropped: it cancels algebraically and |k| is small (no overflow risk).

__device__ __forceinline__ float get_ew(const float* decay, int c){
    float w = decay[c] * (1.0f / (float)Tq);
    return __expf(-__expf(w));
}

// Phase A: per-(b,s,c) chunk-local weighted sums.
// grid (Ss, Bq), block 768 (one channel per thread)
__global__ __launch_bounds__(768) void wkv_chunk(const float* __restrict__ decay)
{
    int s = blockIdx.x, b = blockIdx.y, c = threadIdx.x;
    float ew = get_ew(decay, c);
    size_t base = ((size_t)b*Tq + s*Ls)*Cq + c;

    float fF=0.f, dF=0.f, fB=0.f, dB=0.f, pw=1.f;
    #pragma unroll
    for (int i=0;i<Ls;i++){
        size_t idx = base + (size_t)i*Cq;
        float kk = g_k[idx], vv = g_v[idx];
        float ek = __expf(kk);
        float ekv = ek*vv;
        fF = fmaf(ew, fF, ekv);
        dF = fmaf(ew, dF, ek);
        fB = fmaf(pw, ekv, fB);
        dB = fmaf(pw, ek, dB);
        pw *= ew;
    }
    size_t ci = ((size_t)b*Ss + s)*Cq + c;
    g_cF[ci]=fF; g_cFd[ci]=dF; g_cB[ci]=fB; g_cBd[ci]=dB;
}

// Phase B: scan the Ss chunk carries per (b,c), both directions (exclusive).
__global__ void wkv_carry(const float* __restrict__ decay)
{
    int gid = blockIdx.x * blockDim.x + threadIdx.x;
    if (gid >= NBC) return;
    int b = gid / Cq, c = gid % Cq;
    float ew = get_ew(decay, c);
    float e2 = ew*ew, e4 = e2*e2, e8 = e4*e4, ewL = e8*e8;  // ew^16
    size_t base = (size_t)b*Ss*Cq + c;

    float fin=0.f, fdin=0.f;
    for (int s=0;s<Ss;s++){
        size_t ci = base + (size_t)s*Cq;
        g_Fin[ci]=fin; g_Fdin[ci]=fdin;
        fin  = fmaf(ewL, fin,  g_cF [ci]);
        fdin = fmaf(ewL, fdin, g_cFd[ci]);
    }
    float bin=0.f, bdin=0.f;
    for (int s=Ss-1;s>=0;s--){
        size_t ci = base + (size_t)s*Cq;
        g_Bin[ci]=bin; g_Bdin[ci]=bdin;
        bin  = fmaf(ewL, bin,  g_cB [ci]);
        bdin = fmaf(ewL, bdin, g_cBd[ci]);
    }
}

// Phase C: apply carries, produce y = sr * wkv.
// grid (Ss, Bq*3), block 256: c = (blockIdx.y%3)*256 + tid, b = blockIdx.y/3
__global__ __launch_bounds__(256) void wkv_apply(const float* __restrict__ decay,
                                                 const float* __restrict__ first)
{
    int s = blockIdx.x;
    int b = blockIdx.y / 3;
    int c = (blockIdx.y % 3)*256 + threadIdx.x;
    float ew = get_ew(decay, c);
    float expu = __expf(first[c] * (1.0f / (float)Tq));
    size_t base = ((size_t)b*Tq + s*Ls)*Cq + c;
    size_t ci   = ((size_t)b*Ss + s)*Cq + c;

    float ek[Ls], vv[Ls];
    #pragma unroll
    for (int i=0;i<Ls;i++){
        size_t idx = base + (size_t)i*Cq;
        ek[i] = __expf(g_k[idx]);
        vv[i] = g_v[idx];
    }

    // backward micro-scan (exclusive per element)
    float bnA[Ls], bdA[Ls];
    float bn = g_Bin[ci], bd = g_Bdin[ci];
    #pragma unroll
    for (int i=Ls-1;i>=0;i--){
        bnA[i] = bn; bdA[i] = bd;
        bn = fmaf(ew, bn, ek[i]*vv[i]);
        bd = fmaf(ew, bd, ek[i]);
    }

    // forward micro-scan + combine + sr multiply
    float fn = g_Fin[ci], fd = g_Fdin[ci];
    #pragma unroll
    for (int i=0;i<Ls;i++){
        size_t idx = base + (size_t)i*Cq;
        float eu = expu * ek[i];
        float out = (fn + bnA[i] + eu*vv[i]) / (fd + bdA[i] + eu);
        g_y[idx] = g_sr[idx] * out;
        fn = fmaf(ew, fn, ek[i]*vv[i]);
        fd = fmaf(ew, fd, ek[i]);
    }
}

extern "C" void kernel_launch(void* const* d_in, const int* in_sizes, int n_in,
                              void* d_out, int out_size)
{
    const float* x       = (const float*)d_in[0];
    const float* key_w   = (const float*)d_in[1];
    const float* value_w = (const float*)d_in[2];
    const float* recep_w = (const float*)d_in[3];
    const float* out_w   = (const float*)d_in[4];
    const float* decay   = (const float*)d_in[5];
    const float* first   = (const float*)d_in[6];
    const float* mk      = (const float*)d_in[7];
    const float* mv      = (const float*)d_in[8];
    const float* mr      = (const float*)d_in[9];
    float* out = (float*)d_out;

    // 1) k, v, sr
    dim3 grid1(Cq/BN, Mq/BM, 3);
    gemm_tf32<true><<<grid1, 256>>>(x, key_w, value_w, recep_w, mk, mv, mr, nullptr);

    // 2) chunked bidirectional scan
    wkv_chunk<<<dim3(Ss, Bq), 768>>>(decay);
    wkv_carry<<<NBC/128, 128>>>(decay);
    wkv_apply<<<dim3(Ss, Bq*3), 256>>>(decay, first);

    // 3) out = (sr * rwkv) @ output_w^T
    dim3 grid2(Cq/BN, Mq/BM, 1);
    gemm_tf32<false><<<grid2, 256>>>(nullptr, out_w, nullptr, nullptr,
                                     nullptr, nullptr, nullptr, out);
}

// round 6
// speedup vs baseline: 2.6012x; 1.0529x over previous
#include <cuda_runtime.h>

// Problem constants
#define Bq 16
#define Tq 1024
#define Cq 768
#define Mq (Bq*Tq)          // 16384
#define NBC (Bq*Cq)         // 12288
#define Ls 16               // chunk length
#define Ss 64               // num chunks (Ls*Ss == Tq)
#define WN (Cq*Cq)          // 589824 weight elements

// -------- device scratch (static, no allocations) --------
__device__ float g_k [12582912];   // holds exp(k) after k-GEMM
__device__ float g_v [12582912];
__device__ float g_sr[12582912];
__device__ float g_y [12582912];
__device__ float g_w [4*WN];       // tf32-prerounded weights: k,v,r,o
// chunk carries: [Bq][Ss][Cq]
#define CHN (Bq*Ss*Cq)
__device__ float g_cF [CHN];
__device__ float g_cFd[CHN];
__device__ float g_cB [CHN];
__device__ float g_cBd[CHN];
__device__ float g_Fin [CHN];
__device__ float g_Fdin[CHN];
__device__ float g_Bin [CHN];
__device__ float g_Bdin[CHN];

// -------- tf32 / async helpers --------
__device__ __forceinline__ float to_tf32(float f){
    unsigned u;
    asm("cvt.rna.tf32.f32 %0, %1;" : "=r"(u) : "f"(f));
    return __uint_as_float(u);
}

__device__ __forceinline__ void cp_async16(float* smem_dst, const float* gmem_src){
    unsigned s = (unsigned)__cvta_generic_to_shared(smem_dst);
    asm volatile("cp.async.ca.shared.global [%0], [%1], 16;\n" :: "r"(s), "l"(gmem_src));
}
#define CP_COMMIT() asm volatile("cp.async.commit_group;\n" ::: "memory")
#define CP_WAIT0()  asm volatile("cp.async.wait_group 0;\n" ::: "memory")

__device__ __forceinline__ void mma8(float d[4], const float a[4], const float b[2]){
    const unsigned* A  = reinterpret_cast<const unsigned*>(a);
    const unsigned* Bb = reinterpret_cast<const unsigned*>(b);
    asm volatile(
      "mma.sync.aligned.m16n8k8.row.col.f32.tf32.tf32.f32 "
      "{%0,%1,%2,%3}, {%4,%5,%6,%7}, {%8,%9}, {%0,%1,%2,%3};\n"
      : "+f"(d[0]), "+f"(d[1]), "+f"(d[2]), "+f"(d[3])
      : "r"(A[0]), "r"(A[1]), "r"(A[2]), "r"(A[3]), "r"(Bb[0]), "r"(Bb[1]));
}

// -------- weight prep: RNA-round all 4 weight matrices to tf32 --------
__global__ void prep_w(const float* __restrict__ wk, const float* __restrict__ wv,
                       const float* __restrict__ wr, const float* __restrict__ wo)
{
    int i = blockIdx.x * blockDim.x + threadIdx.x;
    if (i >= WN) return;
    g_w[i       ] = to_tf32(wk[i]);
    g_w[i +   WN] = to_tf32(wv[i]);
    g_w[i + 2*WN] = to_tf32(wr[i]);
    g_w[i + 3*WN] = to_tf32(wo[i]);
}

// -------- GEMM: C[m,n] = sum_k A[m,k] * W[n,k] --------
// XOR-swizzled smem layout, pitch 32 floats: idx = row*32 + ((col4 ^ (row&7))<<2) + col&3.
// Conflict-free for 16B stores and for mma fragment reads (banks 4*(col4^grp8)+c4).
#define BM 128
#define BN 128
#define BK 32
#define NKI (Cq/BK)   // 24

__device__ __forceinline__ int sw_idx(int row, int col4, int c){
    return row*32 + ((col4 ^ (row & 7)) << 2) + c;
}

template<bool MIXED>
__global__ __launch_bounds__(256, 2) void gemm_tf32(
    const float* __restrict__ x,
    const float* __restrict__ mk, const float* __restrict__ mv, const float* __restrict__ mr,
    float* __restrict__ Cext)
{
    __shared__ float As[BM*32];        // single buffer (4096 floats)
    __shared__ float Bs[2*BN*32];      // double buffer (8192 floats)  -> total 48KB

    const float* W;
    const float* mix = nullptr;
    float* Cout;
    const float* Ap;
    int z = MIXED ? blockIdx.z : 0;
    if (MIXED) {
        W    = g_w + (size_t)z*WN;
        mix  = (z==0) ? mk : (z==1) ? mv : mr;
        Cout = (z==0) ? g_k : (z==1) ? g_v : g_sr;
        Ap   = x;
    } else {
        W = g_w + (size_t)3*WN; Cout = Cext; Ap = g_y;
    }

    const int m0 = blockIdx.y * BM;
    const int n0 = blockIdx.x * BN;
    const int tid  = threadIdx.x;
    const int lane = tid & 31;
    const int wid  = tid >> 5;
    const int wm = wid & 3;
    const int wn = wid >> 2;
    const int grp8 = lane >> 2;
    const int c4   = lane & 3;
    const int lrow = tid >> 3;        // 0..31
    const int lk4  = tid & 7;         // col4 index 0..7
    const int lk   = lk4 << 2;        // 0,4,..,28

    float4 aR[4];

    // ---- A tile loader: global -> registers (fused q_shift + mix) ----
    auto loadA = [&](int kt){
        #pragma unroll
        for (int p=0;p<4;p++){
            int row = p*32 + lrow;
            int m = m0 + row;
            int kk = kt + lk;
            float4 a4;
            if (MIXED) {
                int t  = m & (Tq-1);
                int bb = m >> 10;
                int grp = kk / 192;
                int wq = t & 31, hq = t >> 5;
                int tt; bool valid;
                if      (grp==0) { tt = t-1;  valid = (wq > 0);  }
                else if (grp==1) { tt = t+1;  valid = (wq < 31); }
                else if (grp==2) { tt = t-32; valid = (hq > 0);  }
                else             { tt = t+32; valid = (hq < 31); }
                float4 xv = *reinterpret_cast<const float4*>(Ap + (size_t)m*Cq + kk);
                float4 xs = make_float4(0.f,0.f,0.f,0.f);
                if (valid)
                    xs = *reinterpret_cast<const float4*>(Ap + ((size_t)(bb<<10) + tt)*Cq + kk);
                float4 mx = *reinterpret_cast<const float4*>(mix + kk);
                a4.x = mx.x*(xv.x - xs.x) + xs.x;
                a4.y = mx.y*(xv.y - xs.y) + xs.y;
                a4.z = mx.z*(xv.z - xs.z) + xs.z;
                a4.w = mx.w*(xv.w - xs.w) + xs.w;
            } else {
                a4 = *reinterpret_cast<const float4*>(Ap + (size_t)m*Cq + kk);
            }
            aR[p].x = to_tf32(a4.x); aR[p].y = to_tf32(a4.y);
            aR[p].z = to_tf32(a4.z); aR[p].w = to_tf32(a4.w);
        }
    };
    auto storeA = [&](){
        #pragma unroll
        for (int p=0;p<4;p++){
            int row = p*32 + lrow;
            *reinterpret_cast<float4*>(&As[sw_idx(row, lk4, 0)]) = aR[p];
        }
    };
    // ---- B tile: cp.async into swizzled layout ----
    auto loadB = [&](int buf, int kt){
        float* base = Bs + buf*BN*32;
        #pragma unroll
        for (int p=0;p<4;p++){
            int n = p*32 + lrow;
            cp_async16(base + sw_idx(n, lk4, 0), W + (size_t)(n0+n)*Cq + kt + lk);
        }
    };

    float acc[2][8][4];
    #pragma unroll
    for (int i=0;i<2;i++)
      #pragma unroll
      for (int j=0;j<8;j++)
        #pragma unroll
        for (int q=0;q<4;q++) acc[i][j][q] = 0.f;

    // prologue
    loadA(0);
    loadB(0, 0); CP_COMMIT();
    storeA();
    CP_WAIT0();
    __syncthreads();

    for (int it = 0; it < NKI; it++){
        int cur = it & 1;
        if (it + 1 < NKI){
            loadB(cur^1, (it+1)*BK); CP_COMMIT();
            loadA((it+1)*BK);
        }

        const float* Bb = Bs + cur*BN*32;
        #pragma unroll
        for (int ks=0; ks<4; ks++){
            int kb4 = ks*2;     // col4 of low half; +1 for high half
            float af[2][4];
            #pragma unroll
            for (int i=0;i<2;i++){
                int r = wm*32 + i*16;
                af[i][0] = As[sw_idx(r+grp8,   kb4,   c4)];
                af[i][1] = As[sw_idx(r+grp8+8, kb4,   c4)];
                af[i][2] = As[sw_idx(r+grp8,   kb4+1, c4)];
                af[i][3] = As[sw_idx(r+grp8+8, kb4+1, c4)];
            }
            float bf[8][2];
            #pragma unroll
            for (int j=0;j<8;j++){
                int n = wn*64 + j*8 + grp8;
                bf[j][0] = Bb[sw_idx(n, kb4,   c4)];
                bf[j][1] = Bb[sw_idx(n, kb4+1, c4)];
            }
            #pragma unroll
            for (int i=0;i<2;i++)
                #pragma unroll
                for (int j=0;j<8;j++)
                    mma8(acc[i][j], af[i], bf[j]);
        }

        __syncthreads();               // readers of As done
        if (it + 1 < NKI){
            storeA();                  // overwrite single A buffer
            CP_WAIT0();                // next B buffer landed
        }
        __syncthreads();
    }

    // ---- epilogue ----
    #pragma unroll
    for (int i=0;i<2;i++){
        int r = m0 + wm*32 + i*16 + grp8;
        #pragma unroll
        for (int j=0;j<8;j++){
            int col = n0 + wn*64 + j*8 + 2*c4;
            float v0 = acc[i][j][0], v1 = acc[i][j][1];
            float v2 = acc[i][j][2], v3 = acc[i][j][3];
            if (MIXED && z == 0){   // store exp(k) directly
                v0 = __expf(v0); v1 = __expf(v1);
                v2 = __expf(v2); v3 = __expf(v3);
            }
            if (MIXED && z == 2){
                v0 = 1.f/(1.f+__expf(-v0)); v1 = 1.f/(1.f+__expf(-v1));
                v2 = 1.f/(1.f+__expf(-v2)); v3 = 1.f/(1.f+__expf(-v3));
            }
            *reinterpret_cast<float2*>(Cout + (size_t)r*Cq + col)     = make_float2(v0, v1);
            *reinterpret_cast<float2*>(Cout + (size_t)(r+8)*Cq + col) = make_float2(v2, v3);
        }
    }
}

// ================= chunked bi_wkv scan (g_k holds exp(k)) =================
__device__ __forceinline__ float get_ew(const float* decay, int c){
    float w = decay[c] * (1.0f / (float)Tq);
    return __expf(-__expf(w));
}

// Phase A: per-(b,s,c) chunk-local weighted sums. grid (Ss, Bq), block 768
__global__ __launch_bounds__(768) void wkv_chunk(const float* __restrict__ decay)
{
    int s = blockIdx.x, b = blockIdx.y, c = threadIdx.x;
    float ew = get_ew(decay, c);
    size_t base = ((size_t)b*Tq + s*Ls)*Cq + c;

    float fF=0.f, dF=0.f, fB=0.f, dB=0.f, pw=1.f;
    #pragma unroll
    for (int i=0;i<Ls;i++){
        size_t idx = base + (size_t)i*Cq;
        float ek = g_k[idx], vv = g_v[idx];
        float ekv = ek*vv;
        fF = fmaf(ew, fF, ekv);
        dF = fmaf(ew, dF, ek);
        fB = fmaf(pw, ekv, fB);
        dB = fmaf(pw, ek, dB);
        pw *= ew;
    }
    size_t ci = ((size_t)b*Ss + s)*Cq + c;
    g_cF[ci]=fF; g_cFd[ci]=dF; g_cB[ci]=fB; g_cBd[ci]=dB;
}

// Phase B: scan the Ss chunk carries per (b,c), both directions (exclusive).
__global__ void wkv_carry(const float* __restrict__ decay)
{
    int gid = blockIdx.x * blockDim.x + threadIdx.x;
    if (gid >= NBC) return;
    int b = gid / Cq, c = gid % Cq;
    float ew = get_ew(decay, c);
    float e2 = ew*ew, e4 = e2*e2, e8 = e4*e4, ewL = e8*e8;  // ew^16
    size_t base = (size_t)b*Ss*Cq + c;

    float fin=0.f, fdin=0.f;
    for (int s=0;s<Ss;s++){
        size_t ci = base + (size_t)s*Cq;
        g_Fin[ci]=fin; g_Fdin[ci]=fdin;
        fin  = fmaf(ewL, fin,  g_cF [ci]);
        fdin = fmaf(ewL, fdin, g_cFd[ci]);
    }
    float bin=0.f, bdin=0.f;
    for (int s=Ss-1;s>=0;s--){
        size_t ci = base + (size_t)s*Cq;
        g_Bin[ci]=bin; g_Bdin[ci]=bdin;
        bin  = fmaf(ewL, bin,  g_cB [ci]);
        bdin = fmaf(ewL, bdin, g_cBd[ci]);
    }
}

// Phase C: apply carries, produce y = sr * wkv. grid (Ss, Bq*3), block 256
__global__ __launch_bounds__(256) void wkv_apply(const float* __restrict__ decay,
                                                 const float* __restrict__ first)
{
    int s = blockIdx.x;
    int b = blockIdx.y / 3;
    int c = (blockIdx.y % 3)*256 + threadIdx.x;
    float ew = get_ew(decay, c);
    float expu = __expf(first[c] * (1.0f / (float)Tq));
    size_t base = ((size_t)b*Tq + s*Ls)*Cq + c;
    size_t ci   = ((size_t)b*Ss + s)*Cq + c;

    // backward micro-scan (exclusive per element)
    float bnA[Ls], bdA[Ls];
    float bn = g_Bin[ci], bd = g_Bdin[ci];
    #pragma unroll
    for (int i=Ls-1;i>=0;i--){
        size_t idx = base + (size_t)i*Cq;
        float ek = g_k[idx], vv = g_v[idx];
        bnA[i] = bn; bdA[i] = bd;
        bn = fmaf(ew, bn, ek*vv);
        bd = fmaf(ew, bd, ek);
    }

    // forward micro-scan + combine + sr multiply (k,v reload -> L1/L2 hits)
    float fn = g_Fin[ci], fd = g_Fdin[ci];
    #pragma unroll
    for (int i=0;i<Ls;i++){
        size_t idx = base + (size_t)i*Cq;
        float ek = g_k[idx], vv = g_v[idx];
        float eu = expu * ek;
        float out = (fn + bnA[i] + eu*vv) / (fd + bdA[i] + eu);
        g_y[idx] = g_sr[idx] * out;
        fn = fmaf(ew, fn, ek*vv);
        fd = fmaf(ew, fd, ek);
    }
}

extern "C" void kernel_launch(void* const* d_in, const int* in_sizes, int n_in,
                              void* d_out, int out_size)
{
    const float* x       = (const float*)d_in[0];
    const float* key_w   = (const float*)d_in[1];
    const float* value_w = (const float*)d_in[2];
    const float* recep_w = (const float*)d_in[3];
    const float* out_w   = (const float*)d_in[4];
    const float* decay   = (const float*)d_in[5];
    const float* first   = (const float*)d_in[6];
    const float* mk      = (const float*)d_in[7];
    const float* mv      = (const float*)d_in[8];
    const float* mr      = (const float*)d_in[9];
    float* out = (float*)d_out;

    // 0) pre-round weights to tf32
    prep_w<<<(WN+255)/256, 256>>>(key_w, value_w, recep_w, out_w);

    // 1) exp(k), v, sr
    dim3 grid1(Cq/BN, Mq/BM, 3);
    gemm_tf32<true><<<grid1, 256>>>(x, mk, mv, mr, nullptr);

    // 2) chunked bidirectional scan
    wkv_chunk<<<dim3(Ss, Bq), 768>>>(decay);
    wkv_carry<<<NBC/128, 128>>>(decay);
    wkv_apply<<<dim3(Ss, Bq*3), 256>>>(decay, first);

    // 3) out = (sr * rwkv) @ output_w^T
    dim3 grid2(Cq/BN, Mq/BM, 1);
    gemm_tf32<false><<<grid2, 256>>>(nullptr, nullptr, nullptr, nullptr, out);
}

// round 7
// speedup vs baseline: 2.6950x; 1.0361x over previous
#include <cuda_runtime.h>

// Problem constants
#define Bq 16
#define Tq 1024
#define Cq 768
#define Mq (Bq*Tq)          // 16384
#define NBC (Bq*Cq)         // 12288
#define Ls 16               // chunk length
#define Ss 64               // num chunks (Ls*Ss == Tq)
#define WN (Cq*Cq)          // 589824 weight elements

// -------- device scratch (static, no allocations) --------
__device__ float g_k [12582912];   // holds exp(k) after k-GEMM
__device__ float g_v [12582912];
__device__ float g_sr[12582912];
__device__ float g_y [12582912];
__device__ float g_w [4*WN];       // tf32-prerounded weights: k,v,r,o
// chunk carries: [Bq][Ss][Cq]
#define CHN (Bq*Ss*Cq)
__device__ float g_cF [CHN];
__device__ float g_cFd[CHN];
__device__ float g_cB [CHN];
__device__ float g_cBd[CHN];
__device__ float g_Fin [CHN];
__device__ float g_Fdin[CHN];
__device__ float g_Bin [CHN];
__device__ float g_Bdin[CHN];

// -------- tf32 / async helpers --------
__device__ __forceinline__ float to_tf32(float f){
    unsigned u;
    asm("cvt.rna.tf32.f32 %0, %1;" : "=r"(u) : "f"(f));
    return __uint_as_float(u);
}

__device__ __forceinline__ void cp_async16(float* smem_dst, const float* gmem_src){
    unsigned s = (unsigned)__cvta_generic_to_shared(smem_dst);
    asm volatile("cp.async.ca.shared.global [%0], [%1], 16;\n" :: "r"(s), "l"(gmem_src));
}
#define CP_COMMIT() asm volatile("cp.async.commit_group;\n" ::: "memory")
#define CP_WAIT0()  asm volatile("cp.async.wait_group 0;\n" ::: "memory")

__device__ __forceinline__ void mma8(float d[4], const float a[4], const float b[2]){
    const unsigned* A  = reinterpret_cast<const unsigned*>(a);
    const unsigned* Bb = reinterpret_cast<const unsigned*>(b);
    asm volatile(
      "mma.sync.aligned.m16n8k8.row.col.f32.tf32.tf32.f32 "
      "{%0,%1,%2,%3}, {%4,%5,%6,%7}, {%8,%9}, {%0,%1,%2,%3};\n"
      : "+f"(d[0]), "+f"(d[1]), "+f"(d[2]), "+f"(d[3])
      : "r"(A[0]), "r"(A[1]), "r"(A[2]), "r"(A[3]), "r"(Bb[0]), "r"(Bb[1]));
}

// -------- weight prep: RNA-round all 4 weight matrices to tf32 --------
__global__ void prep_w(const float* __restrict__ wk, const float* __restrict__ wv,
                       const float* __restrict__ wr, const float* __restrict__ wo)
{
    int i = blockIdx.x * blockDim.x + threadIdx.x;
    if (i >= WN) return;
    g_w[i       ] = to_tf32(wk[i]);
    g_w[i +   WN] = to_tf32(wv[i]);
    g_w[i + 2*WN] = to_tf32(wr[i]);
    g_w[i + 3*WN] = to_tf32(wo[i]);
}

// -------- GEMM: C[m,n] = sum_k A[m,k] * W[n,k] --------
// XOR-swizzled smem layout, pitch 32 floats: idx = row*32 + ((col4 ^ (row&7))<<2) + col&3.
#define BM 128
#define BN 128
#define BK 32
#define NKI (Cq/BK)   // 24

__device__ __forceinline__ int sw_idx(int row, int col4, int c){
    return row*32 + ((col4 ^ (row & 7)) << 2) + c;
}

template<bool MIXED>
__global__ __launch_bounds__(256, 2) void gemm_tf32(
    const float* __restrict__ x,
    const float* __restrict__ mk, const float* __restrict__ mv, const float* __restrict__ mr,
    float* __restrict__ Cext)
{
    __shared__ float As[BM*32];        // single buffer
    __shared__ float Bs[2*BN*32];      // double buffer  -> total 48KB

    const float* W;
    const float* mix = nullptr;
    float* Cout;
    const float* Ap;
    int z = MIXED ? blockIdx.z : 0;
    if (MIXED) {
        W    = g_w + (size_t)z*WN;
        mix  = (z==0) ? mk : (z==1) ? mv : mr;
        Cout = (z==0) ? g_k : (z==1) ? g_v : g_sr;
        Ap   = x;
    } else {
        W = g_w + (size_t)3*WN; Cout = Cext; Ap = g_y;
    }

    const int m0 = blockIdx.y * BM;
    const int n0 = blockIdx.x * BN;
    const int tid  = threadIdx.x;
    const int lane = tid & 31;
    const int wid  = tid >> 5;
    const int wm = wid & 3;
    const int wn = wid >> 2;
    const int grp8 = lane >> 2;
    const int c4   = lane & 3;
    const int lrow = tid >> 3;        // 0..31
    const int lk4  = tid & 7;         // col4 index 0..7
    const int lk   = lk4 << 2;        // 0,4,..,28

    float4 aR[4];

    auto loadA = [&](int kt){
        #pragma unroll
        for (int p=0;p<4;p++){
            int row = p*32 + lrow;
            int m = m0 + row;
            int kk = kt + lk;
            float4 a4;
            if (MIXED) {
                int t  = m & (Tq-1);
                int bb = m >> 10;
                int grp = kk / 192;
                int wq = t & 31, hq = t >> 5;
                int tt; bool valid;
                if      (grp==0) { tt = t-1;  valid = (wq > 0);  }
                else if (grp==1) { tt = t+1;  valid = (wq < 31); }
                else if (grp==2) { tt = t-32; valid = (hq > 0);  }
                else             { tt = t+32; valid = (hq < 31); }
                float4 xv = *reinterpret_cast<const float4*>(Ap + (size_t)m*Cq + kk);
                float4 xs = make_float4(0.f,0.f,0.f,0.f);
                if (valid)
                    xs = *reinterpret_cast<const float4*>(Ap + ((size_t)(bb<<10) + tt)*Cq + kk);
                float4 mx = *reinterpret_cast<const float4*>(mix + kk);
                a4.x = mx.x*(xv.x - xs.x) + xs.x;
                a4.y = mx.y*(xv.y - xs.y) + xs.y;
                a4.z = mx.z*(xv.z - xs.z) + xs.z;
                a4.w = mx.w*(xv.w - xs.w) + xs.w;
            } else {
                a4 = *reinterpret_cast<const float4*>(Ap + (size_t)m*Cq + kk);
            }
            aR[p].x = to_tf32(a4.x); aR[p].y = to_tf32(a4.y);
            aR[p].z = to_tf32(a4.z); aR[p].w = to_tf32(a4.w);
        }
    };
    auto storeA = [&](){
        #pragma unroll
        for (int p=0;p<4;p++){
            int row = p*32 + lrow;
            *reinterpret_cast<float4*>(&As[sw_idx(row, lk4, 0)]) = aR[p];
        }
    };
    auto loadB = [&](int buf, int kt){
        float* base = Bs + buf*BN*32;
        #pragma unroll
        for (int p=0;p<4;p++){
            int n = p*32 + lrow;
            cp_async16(base + sw_idx(n, lk4, 0), W + (size_t)(n0+n)*Cq + kt + lk);
        }
    };

    float acc[2][8][4];
    #pragma unroll
    for (int i=0;i<2;i++)
      #pragma unroll
      for (int j=0;j<8;j++)
        #pragma unroll
        for (int q=0;q<4;q++) acc[i][j][q] = 0.f;

    // prologue
    loadA(0);
    loadB(0, 0); CP_COMMIT();
    storeA();
    CP_WAIT0();
    __syncthreads();

    for (int it = 0; it < NKI; it++){
        int cur = it & 1;
        if (it + 1 < NKI){
            loadB(cur^1, (it+1)*BK); CP_COMMIT();
            loadA((it+1)*BK);
        }

        const float* Bb = Bs + cur*BN*32;
        #pragma unroll
        for (int ks=0; ks<4; ks++){
            int kb4 = ks*2;
            float af[2][4];
            #pragma unroll
            for (int i=0;i<2;i++){
                int r = wm*32 + i*16;
                af[i][0] = As[sw_idx(r+grp8,   kb4,   c4)];
                af[i][1] = As[sw_idx(r+grp8+8, kb4,   c4)];
                af[i][2] = As[sw_idx(r+grp8,   kb4+1, c4)];
                af[i][3] = As[sw_idx(r+grp8+8, kb4+1, c4)];
            }
            float bf[8][2];
            #pragma unroll
            for (int j=0;j<8;j++){
                int n = wn*64 + j*8 + grp8;
                bf[j][0] = Bb[sw_idx(n, kb4,   c4)];
                bf[j][1] = Bb[sw_idx(n, kb4+1, c4)];
            }
            #pragma unroll
            for (int i=0;i<2;i++)
                #pragma unroll
                for (int j=0;j<8;j++)
                    mma8(acc[i][j], af[i], bf[j]);
        }

        __syncthreads();
        if (it + 1 < NKI){
            storeA();
            CP_WAIT0();
        }
        __syncthreads();
    }

    #pragma unroll
    for (int i=0;i<2;i++){
        int r = m0 + wm*32 + i*16 + grp8;
        #pragma unroll
        for (int j=0;j<8;j++){
            int col = n0 + wn*64 + j*8 + 2*c4;
            float v0 = acc[i][j][0], v1 = acc[i][j][1];
            float v2 = acc[i][j][2], v3 = acc[i][j][3];
            if (MIXED && z == 0){
                v0 = __expf(v0); v1 = __expf(v1);
                v2 = __expf(v2); v3 = __expf(v3);
            }
            if (MIXED && z == 2){
                v0 = 1.f/(1.f+__expf(-v0)); v1 = 1.f/(1.f+__expf(-v1));
                v2 = 1.f/(1.f+__expf(-v2)); v3 = 1.f/(1.f+__expf(-v3));
            }
            *reinterpret_cast<float2*>(Cout + (size_t)r*Cq + col)     = make_float2(v0, v1);
            *reinterpret_cast<float2*>(Cout + (size_t)(r+8)*Cq + col) = make_float2(v2, v3);
        }
    }
}

// ================= chunked bi_wkv scan (g_k holds exp(k)) =================
__device__ __forceinline__ float get_ew(const float* decay, int c){
    float w = decay[c] * (1.0f / (float)Tq);
    return __expf(-__expf(w));
}

// Phase A: per-(b,s,c) chunk-local weighted sums. grid (Ss, Bq), block 768
__global__ __launch_bounds__(768) void wkv_chunk(const float* __restrict__ decay)
{
    int s = blockIdx.x, b = blockIdx.y, c = threadIdx.x;
    float ew = get_ew(decay, c);
    size_t base = ((size_t)b*Tq + s*Ls)*Cq + c;

    float fF=0.f, dF=0.f, fB=0.f, dB=0.f, pw=1.f;
    #pragma unroll
    for (int i=0;i<Ls;i++){
        size_t idx = base + (size_t)i*Cq;
        float ek = g_k[idx], vv = g_v[idx];
        float ekv = ek*vv;
        fF = fmaf(ew, fF, ekv);
        dF = fmaf(ew, dF, ek);
        fB = fmaf(pw, ekv, fB);
        dB = fmaf(pw, ek, dB);
        pw *= ew;
    }
    size_t ci = ((size_t)b*Ss + s)*Cq + c;
    g_cF[ci]=fF; g_cFd[ci]=dF; g_cB[ci]=fB; g_cBd[ci]=dB;
}

// Phase B: scan the Ss chunk carries per (b,c).
// gridDim.y selects direction (0=fwd, 1=bwd); unrolled for MLP.
__global__ __launch_bounds__(256) void wkv_carry(const float* __restrict__ decay)
{
    int gid = blockIdx.x * blockDim.x + threadIdx.x;
    if (gid >= NBC) return;
    int b = gid / Cq, c = gid % Cq;
    float ew = get_ew(decay, c);
    float e2 = ew*ew, e4 = e2*e2, e8 = e4*e4, ewL = e8*e8;  // ew^16
    size_t base = (size_t)b*Ss*Cq + c;

    if (blockIdx.y == 0){
        float fin=0.f, fdin=0.f;
        #pragma unroll 8
        for (int s=0;s<Ss;s++){
            size_t ci = base + (size_t)s*Cq;
            float cf = g_cF[ci], cfd = g_cFd[ci];
            g_Fin[ci]=fin; g_Fdin[ci]=fdin;
            fin  = fmaf(ewL, fin,  cf);
            fdin = fmaf(ewL, fdin, cfd);
        }
    } else {
        float bin=0.f, bdin=0.f;
        #pragma unroll 8
        for (int s=Ss-1;s>=0;s--){
            size_t ci = base + (size_t)s*Cq;
            float cb = g_cB[ci], cbd = g_cBd[ci];
            g_Bin[ci]=bin; g_Bdin[ci]=bdin;
            bin  = fmaf(ewL, bin,  cb);
            bdin = fmaf(ewL, bdin, cbd);
        }
    }
}

// Phase C: apply carries, produce y = sr * wkv. grid (Ss, Bq*3), block 256
__global__ __launch_bounds__(256) void wkv_apply(const float* __restrict__ decay,
                                                 const float* __restrict__ first)
{
    int s = blockIdx.x;
    int b = blockIdx.y / 3;
    int c = (blockIdx.y % 3)*256 + threadIdx.x;
    float ew = get_ew(decay, c);
    float expu = __expf(first[c] * (1.0f / (float)Tq));
    size_t base = ((size_t)b*Tq + s*Ls)*Cq + c;
    size_t ci   = ((size_t)b*Ss + s)*Cq + c;

    // backward micro-scan (exclusive per element)
    float bnA[Ls], bdA[Ls];
    float bn = g_Bin[ci], bd = g_Bdin[ci];
    #pragma unroll
    for (int i=Ls-1;i>=0;i--){
        size_t idx = base + (size_t)i*Cq;
        float ek = g_k[idx], vv = g_v[idx];
        bnA[i] = bn; bdA[i] = bd;
        bn = fmaf(ew, bn, ek*vv);
        bd = fmaf(ew, bd, ek);
    }

    // forward micro-scan + combine + sr multiply
    float fn = g_Fin[ci], fd = g_Fdin[ci];
    #pragma unroll
    for (int i=0;i<Ls;i++){
        size_t idx = base + (size_t)i*Cq;
        float ek = g_k[idx], vv = g_v[idx];
        float eu = expu * ek;
        float out = (fn + bnA[i] + eu*vv) / (fd + bdA[i] + eu);
        g_y[idx] = g_sr[idx] * out;
        fn = fmaf(ew, fn, ek*vv);
        fd = fmaf(ew, fd, ek);
    }
}

extern "C" void kernel_launch(void* const* d_in, const int* in_sizes, int n_in,
                              void* d_out, int out_size)
{
    const float* x       = (const float*)d_in[0];
    const float* key_w   = (const float*)d_in[1];
    const float* value_w = (const float*)d_in[2];
    const float* recep_w = (const float*)d_in[3];
    const float* out_w   = (const float*)d_in[4];
    const float* decay   = (const float*)d_in[5];
    const float* first   = (const float*)d_in[6];
    const float* mk      = (const float*)d_in[7];
    const float* mv      = (const float*)d_in[8];
    const float* mr      = (const float*)d_in[9];
    float* out = (float*)d_out;

    // 0) pre-round weights to tf32
    prep_w<<<(WN+255)/256, 256>>>(key_w, value_w, recep_w, out_w);

    // 1) exp(k), v, sr
    dim3 grid1(Cq/BN, Mq/BM, 3);
    gemm_tf32<true><<<grid1, 256>>>(x, mk, mv, mr, nullptr);

    // 2) chunked bidirectional scan
    wkv_chunk<<<dim3(Ss, Bq), 768>>>(decay);
    wkv_carry<<<dim3(NBC/256, 2), 256>>>(decay);
    wkv_apply<<<dim3(Ss, Bq*3), 256>>>(decay, first);

    // 3) out = (sr * rwkv) @ output_w^T
    dim3 grid2(Cq/BN, Mq/BM, 1);
    gemm_tf32<false><<<grid2, 256>>>(nullptr, nullptr, nullptr, nullptr, out);
}